// round 5
// baseline (speedup 1.0000x reference)
#include <cuda_runtime.h>
#include <cstdint>
#include <cstddef>

// ---------------------------------------------------------------------------
// PointSampler: jax threefry masked random-permutation sampling.
//   x [B,C,H,W] f32, mask [B,1,H,W] f32, k=4096
//   out = concat( samples[B,k,C], b_idx[B,k], h_idx[B,k], w_idx[B,k] ) f32
// sel_a (threefry+hist) -> sel_b (scan) -> sel_c (scatter) -> sel_d (rank+
// compact+idx) -> gather (register-only, pos-sorted locality)
// ---------------------------------------------------------------------------

constexpr int B = 16, C = 256, H = 128, W = 128;
constexpr int L = H * W;        // 16384
constexpr int K = 4096;
constexpr int NBIN = 16385;     // 16384 key bins + 1 unmasked sentinel
constexpr int Q = 8;            // histogram chunks per batch
constexpr int QELEM = L / Q;    // 2048
constexpr int WIN = K + 128;    // ranked slot window

constexpr int SMEM_A = NBIN * 4;
constexpr int SMEM_B = NBIN * 4;
constexpr int SMEM_D = WIN * 8 + L * 2 + K * 4;

__device__ uint32_t g_mkey[B * L];        // 23-bit key or 0x800000 sentinel
__device__ uint32_t g_hist[B * Q * NBIN];
__device__ uint32_t g_base[B * NBIN];
__device__ uint64_t g_sorted[B * WIN];
__device__ uint32_t g_pos[B * K];         // rank -> flat position
__device__ uint32_t g_sel[B * K];         // pos-sorted: (pos<<16) | rank
__device__ int      g_counts[B];

// ---- jax threefry2x32 (20 rounds), partitionable mode ---------------------
__device__ __forceinline__ uint32_t jax_bits(uint32_t n) {
    uint32_t k0 = 0u, k1 = 42u;
    uint32_t ks2 = k0 ^ k1 ^ 0x1BD11BDAu;
    uint32_t x0 = k0, x1 = n + k1;
#define TF_RND(r) { x0 += x1; x1 = __funnelshift_l(x1, x1, (r)); x1 ^= x0; }
    TF_RND(13) TF_RND(15) TF_RND(26) TF_RND(6)
    x0 += k1;  x1 += ks2 + 1u;
    TF_RND(17) TF_RND(29) TF_RND(16) TF_RND(24)
    x0 += ks2; x1 += k0 + 2u;
    TF_RND(13) TF_RND(15) TF_RND(26) TF_RND(6)
    x0 += k0;  x1 += k1 + 3u;
    TF_RND(17) TF_RND(29) TF_RND(16) TF_RND(24)
    x0 += k1;  x1 += ks2 + 4u;
    TF_RND(13) TF_RND(15) TF_RND(26) TF_RND(6)
    x0 += ks2; x1 += k0 + 5u;
#undef TF_RND
    return x0 ^ x1;
}

__device__ __forceinline__ uint32_t warp_incl_scan(uint32_t v) {
#pragma unroll
    for (int o = 1; o < 32; o <<= 1) {
        uint32_t u = __shfl_up_sync(0xFFFFFFFFu, v, o);
        if ((threadIdx.x & 31) >= o) v += u;
    }
    return v;
}

// ---- sel_a: threefry once -> g_mkey + per-chunk histograms ----------------
__global__ __launch_bounds__(1024) void sel_a(const float* __restrict__ mask) {
    extern __shared__ uint32_t hist[];            // NBIN
    const int b = blockIdx.x >> 3;
    const int q = blockIdx.x & 7;
    const int t = threadIdx.x;
    for (int i = t; i < NBIN; i += 1024) hist[i] = 0u;
    __syncthreads();
#pragma unroll
    for (int i = 0; i < QELEM / 1024; i++) {
        uint32_t n = (uint32_t)(b * L + q * QELEM + t + i * 1024);
        uint32_t bits = jax_bits(n);
        uint32_t mkey = (mask[n] > 0.5f) ? (bits >> 9) : 0x800000u;
        g_mkey[n] = mkey;
        atomicAdd(&hist[mkey >> 9], 1u);
    }
    __syncthreads();
    uint32_t* gh = g_hist + (size_t)blockIdx.x * NBIN;
    for (int i = t; i < NBIN; i += 1024) gh[i] = hist[i];
}

// ---- sel_b: merge + exclusive scan (warp-shuffle) -> g_base, g_counts -----
__global__ __launch_bounds__(1024) void sel_b() {
    extern __shared__ uint32_t tot[];             // NBIN
    __shared__ uint32_t wpre[32], wsum[32];
    const int b = blockIdx.x;
    const int t = threadIdx.x;
    for (int i = t; i < NBIN; i += 1024) {
        uint32_t s = 0;
#pragma unroll
        for (int q = 0; q < Q; q++)
            s += g_hist[((size_t)(b * Q + q)) * NBIN + i];
        tot[i] = s;
    }
    __syncthreads();
    const int start = t * 16;
    const int cnt = (t == 1023) ? 17 : 16;
    uint32_t s = 0;
    for (int i = 0; i < cnt; i++) s += tot[start + i];
    uint32_t incl = warp_incl_scan(s);
    if ((t & 31) == 31) wsum[t >> 5] = incl;
    __syncthreads();
    if (t < 32) {
        uint32_t v = wsum[t];
        uint32_t iv = warp_incl_scan(v);
        wpre[t] = iv - v;
    }
    __syncthreads();
    uint32_t run = wpre[t >> 5] + incl - s;
    for (int i = 0; i < cnt; i++) {
        uint32_t h = tot[start + i];
        tot[start + i] = run;
        run += h;
    }
    __syncthreads();
    for (int i = t; i < NBIN; i += 1024) g_base[b * NBIN + i] = tot[i];
    if (t == 0) g_counts[b] = (int)tot[16384];
}

// ---- sel_c: atomic scatter of masked keys into bin slots ------------------
__global__ __launch_bounds__(1024) void sel_c() {
    const int b = blockIdx.x >> 3;
    const int q = blockIdx.x & 7;
    const int t = threadIdx.x;
#pragma unroll
    for (int i = 0; i < QELEM / 1024; i++) {
        uint32_t n = (uint32_t)(b * L + q * QELEM + t + i * 1024);
        uint32_t mkey = g_mkey[n];
        if (mkey < 0x800000u) {
            uint32_t slot = atomicAdd(&g_base[b * NBIN + (mkey >> 9)], 1u);
            if (slot < (uint32_t)WIN)
                g_sorted[(size_t)b * WIN + slot] =
                    (((uint64_t)mkey) << 14) | (uint64_t)(n & (L - 1));
        }
    }
}

// ---- sel_d: rank window, pos->rank map, compact sel list, idx out ---------
__global__ __launch_bounds__(1024, 1) void sel_d(float* __restrict__ out,
                                                 int out_size) {
    extern __shared__ unsigned char sm[];
    uint64_t* pairs   = (uint64_t*)sm;                              // WIN
    uint16_t* slotm   = (uint16_t*)(sm + (size_t)WIN * 8);          // L
    uint32_t* rankpos = (uint32_t*)(sm + (size_t)WIN * 8 + L * 2);  // K
    __shared__ uint32_t wpre[32], wsum[32];

    const int b = blockIdx.x;
    const int t = threadIdx.x;
    const int count = g_counts[b];
    const int nwin  = (count < WIN) ? count : WIN;
    const int nproc = (count < K + 96) ? count : (K + 96);

    for (int i = t; i < nwin; i += 1024)
        pairs[i] = g_sorted[(size_t)b * WIN + i];
    {
        uint32_t* ss = (uint32_t*)slotm;
        for (int i = t; i < L / 2; i += 1024) ss[i] = 0xFFFFFFFFu;
    }
    __syncthreads();

    for (int sI = t; sI < nproc; sI += 1024) {
        uint64_t kv = pairs[sI];
        uint32_t bn = (uint32_t)(kv >> 23);
        int g = sI;
        while (g > 0 && (uint32_t)(pairs[g - 1] >> 23) == bn) g--;
        int r = 0;
        for (int u = g; u < nwin; u++) {
            uint64_t pk = pairs[u];
            if ((uint32_t)(pk >> 23) != bn) break;
            if (pk < kv) r++;
        }
        int rank = g + r;
        if (rank < K) {
            uint32_t p = (uint32_t)(kv & (uint64_t)(L - 1));
            g_pos[b * K + rank] = p;
            rankpos[rank] = p;
            slotm[p] = (uint16_t)rank;
        }
    }
    __syncthreads();

    // compact pos-sorted (pos<<16)|rank list via warp-shuffle scan
    {
        const int p0 = t * 16;
        uint32_t c2 = 0;
#pragma unroll
        for (int i = 0; i < 16; i++)
            if (slotm[p0 + i] != 0xFFFFu) c2++;
        uint32_t incl = warp_incl_scan(c2);
        if ((t & 31) == 31) wsum[t >> 5] = incl;
        __syncthreads();
        if (t < 32) {
            uint32_t v = wsum[t];
            uint32_t iv = warp_incl_scan(v);
            wpre[t] = iv - v;
        }
        __syncthreads();
        uint32_t base = wpre[t >> 5] + incl - c2;
#pragma unroll
        for (int i = 0; i < 16; i++) {
            uint16_t rk = slotm[p0 + i];
            if (rk != 0xFFFFu)
                g_sel[b * K + (base++)] = ((uint32_t)(p0 + i) << 16) | (uint32_t)rk;
        }
    }

    // (b, h, w) index outputs
    size_t off = (size_t)B * K * C;
    if ((size_t)out_size >= off + 3u * (size_t)(B * K)) {
        for (int j = t; j < K; j += 1024) {
            int eff = (j < count) ? j : (count > 0 ? j % count : 0);
            uint32_t p = rankpos[eff];
            size_t i = (size_t)b * K + j;
            out[off + i] = (float)b;
            out[off + (size_t)(B * K) + i] = (float)(p >> 7);
            out[off + 2u * (size_t)(B * K) + i] = (float)(p & (W - 1));
        }
    }
}

// ---- gather: register-only, pos-sorted read locality, full-sector stores --
__global__ __launch_bounds__(256) void gather_kernel(
        const float* __restrict__ x, float* __restrict__ out) {
    const int ct = blockIdx.x;        // 32 channel tiles of 8
    const int jt = blockIdx.y;        // 16 j tiles of 256
    const int b  = blockIdx.z;
    const int t  = threadIdx.x;
    const int cb = g_counts[b];
    const int nsel = (cb < K) ? cb : K;
    const int c0 = ct * 8;
    const int j = jt * 256 + t;

    if (j < nsel) {
        uint32_t e = __ldg(&g_sel[b * K + j]);
        uint32_t pos = e >> 16;
        uint32_t rank = e & 0xFFFFu;
        const float* px = x + ((size_t)(b * C + c0)) * (size_t)L + pos;
        float v[8];
#pragma unroll
        for (int u = 0; u < 8; u++)
            v[u] = __ldg(px + (size_t)u * (size_t)L);   // 8 planes, MLP=8
        float4 q0 = make_float4(v[0], v[1], v[2], v[3]);
        float4 q1 = make_float4(v[4], v[5], v[6], v[7]);
        float4* o = (float4*)(out + ((size_t)b * K + rank) * (size_t)C + c0);
        o[0] = q0;                                       // one full 32B sector
        o[1] = q1;
    }

    // wrap fallback (count < K) — no-op in practice
    if (cb > 0 && cb < K && jt == 0) {
        for (int j2 = cb + t; j2 < K; j2 += 256) {
            uint32_t p = g_pos[b * K + (j2 % cb)];
#pragma unroll
            for (int cc = 0; cc < 8; cc++)
                out[((size_t)b * K + j2) * (size_t)C + c0 + cc] =
                    __ldg(&x[((size_t)(b * C + c0 + cc)) * (size_t)L + p]);
        }
    }
}

extern "C" void kernel_launch(void* const* d_in, const int* in_sizes, int n_in,
                              void* d_out, int out_size) {
    const float* x = (const float*)d_in[0];
    int mi = n_in - 1;
    for (int i = 1; i < n_in; i++)
        if (in_sizes[i] == B * L) { mi = i; break; }
    const float* mask = (const float*)d_in[mi];
    float* out = (float*)d_out;

    static bool attr_done = false;
    if (!attr_done) {
        cudaFuncSetAttribute(sel_a, cudaFuncAttributeMaxDynamicSharedMemorySize, SMEM_A);
        cudaFuncSetAttribute(sel_b, cudaFuncAttributeMaxDynamicSharedMemorySize, SMEM_B);
        cudaFuncSetAttribute(sel_d, cudaFuncAttributeMaxDynamicSharedMemorySize, SMEM_D);
        attr_done = true;
    }

    sel_a<<<B * Q, 1024, SMEM_A>>>(mask);
    sel_b<<<B, 1024, SMEM_B>>>();
    sel_c<<<B * Q, 1024>>>();
    sel_d<<<B, 1024, SMEM_D>>>(out, out_size);
    dim3 gg(C / 8, K / 256, B);
    gather_kernel<<<gg, 256>>>(x, out);
}

// round 6
// speedup vs baseline: 1.3307x; 1.3307x over previous
#include <cuda_runtime.h>
#include <cstdint>
#include <cstddef>

// ---------------------------------------------------------------------------
// PointSampler: jax threefry masked random-permutation sampling.
//   x [B,C,H,W] f32, mask [B,1,H,W] f32, k=4096
//   out = concat( samples[B,k,C], b_idx[B,k], h_idx[B,k], w_idx[B,k] ) f32
// select (1 kernel, 16 CTAs, all-smem counting sort) ->
// gather (tiled transpose: coalesced reads AND coalesced writes)
// ---------------------------------------------------------------------------

constexpr int B = 16, C = 256, H = 128, W = 128;
constexpr int L = H * W;          // 16384
constexpr int K = 4096;
constexpr int NB = 4096;          // bins = mkey>>11, avg ~2 elems/bin
constexpr int WIN = K + 256;      // scatter window (slack >> max bin size)
constexpr int NPROC = K + 128;    // slots ranked

constexpr int SMEM_SEL = 65536 + NB * 4 + WIN * 8;   // mkey + hist + pairs

__device__ uint32_t g_pos[B * K];        // rank -> flat position
__device__ uint32_t g_sel[B * K];        // pos-sorted: (pos<<16) | rank
__device__ uint32_t g_cidx[B * 1025];    // sel-index at 16-pos granularity
__device__ int      g_counts[B];

// ---- jax threefry2x32 (20 rounds), partitionable mode ---------------------
__device__ __forceinline__ uint32_t jax_bits(uint32_t n) {
    uint32_t k0 = 0u, k1 = 42u;
    uint32_t ks2 = k0 ^ k1 ^ 0x1BD11BDAu;
    uint32_t x0 = k0, x1 = n + k1;
#define TF_RND(r) { x0 += x1; x1 = __funnelshift_l(x1, x1, (r)); x1 ^= x0; }
    TF_RND(13) TF_RND(15) TF_RND(26) TF_RND(6)
    x0 += k1;  x1 += ks2 + 1u;
    TF_RND(17) TF_RND(29) TF_RND(16) TF_RND(24)
    x0 += ks2; x1 += k0 + 2u;
    TF_RND(13) TF_RND(15) TF_RND(26) TF_RND(6)
    x0 += k0;  x1 += k1 + 3u;
    TF_RND(17) TF_RND(29) TF_RND(16) TF_RND(24)
    x0 += k1;  x1 += ks2 + 4u;
    TF_RND(13) TF_RND(15) TF_RND(26) TF_RND(6)
    x0 += ks2; x1 += k0 + 5u;
#undef TF_RND
    return x0 ^ x1;
}

__device__ __forceinline__ uint32_t warp_incl_scan(uint32_t v) {
#pragma unroll
    for (int o = 1; o < 32; o <<= 1) {
        uint32_t u = __shfl_up_sync(0xFFFFFFFFu, v, o);
        if ((threadIdx.x & 31) >= o) v += u;
    }
    return v;
}

// ---- select: everything for one batch in one CTA's smem -------------------
__global__ __launch_bounds__(1024, 1) void select_kernel(
        const float* __restrict__ mask, float* __restrict__ out, int out_size) {
    extern __shared__ unsigned char sm[];
    uint32_t* mkey   = (uint32_t*)sm;                       // 16384 u32 (64KB)
    uint32_t* hist   = (uint32_t*)(sm + 65536);             // NB u32
    uint64_t* pairs  = (uint64_t*)(sm + 65536 + NB * 4);    // WIN u64
    uint16_t* slotm  = (uint16_t*)sm;                       // alias (post-scatter)
    uint32_t* rankpos = (uint32_t*)(sm + 32768);            // alias (post-scatter)
    __shared__ uint32_t wsum[32], wpre[32];
    __shared__ int sh_count;

    const int b = blockIdx.x;
    const int t = threadIdx.x;

    for (int i = t; i < NB; i += 1024) hist[i] = 0u;
    __syncthreads();

    // phase 1: threefry -> mkey (smem) + histogram of masked keys
#pragma unroll
    for (int i = 0; i < 16; i++) {
        int l = i * 1024 + t;
        uint32_t bits = jax_bits((uint32_t)(b * L + l));
        uint32_t mk = (mask[b * L + l] > 0.5f) ? (bits >> 9) : 0x800000u;
        mkey[l] = mk;
        if (mk < 0x800000u) atomicAdd(&hist[mk >> 11], 1u);
    }
    __syncthreads();

    // phase 2: exclusive scan of 4096 bins (warp shuffles, 2 barriers)
    uint32_t h4[4];
    uint32_t s = 0;
#pragma unroll
    for (int i = 0; i < 4; i++) { h4[i] = hist[t * 4 + i]; s += h4[i]; }
    uint32_t incl = warp_incl_scan(s);
    if ((t & 31) == 31) wsum[t >> 5] = incl;
    __syncthreads();
    if (t < 32) { uint32_t v = wsum[t]; uint32_t iv = warp_incl_scan(v); wpre[t] = iv - v; }
    __syncthreads();
    uint32_t run = wpre[t >> 5] + incl - s;
#pragma unroll
    for (int i = 0; i < 4; i++) { hist[t * 4 + i] = run; run += h4[i]; }
    if (t == 1023) sh_count = (int)run;
    __syncthreads();
    const int count = sh_count;
    if (t == 0) g_counts[b] = count;

    // phase 3: scatter masked keys into bin slots (window only)
#pragma unroll
    for (int i = 0; i < 16; i++) {
        int l = i * 1024 + t;
        uint32_t mk = mkey[l];
        if (mk < 0x800000u) {
            uint32_t slot = atomicAdd(&hist[mk >> 11], 1u);
            if (slot < (uint32_t)WIN)
                pairs[slot] = (((uint64_t)mk) << 14) | (uint64_t)l;
        }
    }
    __syncthreads();

    // phase 4: init pos->rank map (mkey region now dead)
    {
        uint32_t* ss = (uint32_t*)slotm;
        for (int i = t; i < L / 2; i += 1024) ss[i] = 0xFFFFFFFFu;
    }
    __syncthreads();

    // phase 5: rank fixup (total order by (mkey,pos) within each bin)
    const int nwin  = (count < WIN) ? count : WIN;
    const int nproc = (count < NPROC) ? count : NPROC;
    for (int sI = t; sI < nproc; sI += 1024) {
        uint64_t kv = pairs[sI];
        uint32_t bn = (uint32_t)(kv >> 25);
        int g = sI;
        while (g > 0 && (uint32_t)(pairs[g - 1] >> 25) == bn) g--;
        int r = 0;
        for (int u = g; u < nwin; u++) {
            uint64_t pk = pairs[u];
            if ((uint32_t)(pk >> 25) != bn) break;
            if (pk < kv) r++;
        }
        int rank = g + r;
        if (rank < K) {
            uint32_t p = (uint32_t)(kv & (uint64_t)(L - 1));
            g_pos[b * K + rank] = p;
            rankpos[rank] = p;
            slotm[p] = (uint16_t)rank;
        }
    }
    __syncthreads();

    // phase 6: compaction -> pos-sorted g_sel + 16-pos-granular g_cidx
    {
        const int p0 = t * 16;
        uint32_t c2 = 0;
#pragma unroll
        for (int i = 0; i < 16; i++)
            if (slotm[p0 + i] != 0xFFFFu) c2++;
        uint32_t incl2 = warp_incl_scan(c2);
        if ((t & 31) == 31) wsum[t >> 5] = incl2;
        __syncthreads();
        if (t < 32) { uint32_t v = wsum[t]; uint32_t iv = warp_incl_scan(v); wpre[t] = iv - v; }
        __syncthreads();
        uint32_t base = wpre[t >> 5] + incl2 - c2;
        g_cidx[b * 1025 + t] = base;
        if (t == 1023) g_cidx[b * 1025 + 1024] = base + c2;
#pragma unroll
        for (int i = 0; i < 16; i++) {
            uint16_t rk = slotm[p0 + i];
            if (rk != 0xFFFFu)
                g_sel[b * K + (base++)] = ((uint32_t)(p0 + i) << 16) | (uint32_t)rk;
        }
    }

    // phase 7: (b, h, w) index outputs
    size_t off = (size_t)B * K * C;
    if ((size_t)out_size >= off + 3u * (size_t)(B * K) && count > 0) {
        for (int j = t; j < K; j += 1024) {
            int eff = (j < count) ? j : (j % count);
            uint32_t p = rankpos[eff];
            size_t i = (size_t)b * K + j;
            out[off + i] = (float)b;
            out[off + (size_t)(B * K) + i] = (float)(p >> 7);
            out[off + 2u * (size_t)(B * K) + i] = (float)(p & (W - 1));
        }
    }
}

// ---- gather: tiled transpose, coalesced reads + coalesced writes ----------
__global__ __launch_bounds__(256) void gather_kernel(
        const float* __restrict__ x, float* __restrict__ out) {
    __shared__ float tile[32][129];          // [channel][pos], pad -> no conflicts

    const int pblk = blockIdx.x;             // 4 pos-blocks of 4096
    const int cblk = blockIdx.y;             // 8 c-blocks of 32
    const int b    = blockIdx.z;
    const int t = threadIdx.x;
    const int w = t >> 5, lane = t & 31;

    const int cb = g_counts[b];
    const int nsel = (cb < K) ? cb : K;
    const int c0 = cblk * 32;
    const float* xb = x + ((size_t)(b * C + c0)) * (size_t)L;
    const int pbase0 = pblk * 4096;

    for (int pw = 0; pw < 32; pw++) {
        const int pbase = pbase0 + pw * 128;

        // load 32 channels x 128 pos, fully coalesced (float4 per lane)
        float4 v[4];
#pragma unroll
        for (int r = 0; r < 4; r++) {
            int row = w + 8 * r;
            v[r] = __ldg((const float4*)(xb + (size_t)row * L + pbase) + lane);
        }
#pragma unroll
        for (int r = 0; r < 4; r++) {
            int row = w + 8 * r;
            tile[row][lane * 4 + 0] = v[r].x;
            tile[row][lane * 4 + 1] = v[r].y;
            tile[row][lane * 4 + 2] = v[r].z;
            tile[row][lane * 4 + 3] = v[r].w;
        }
        __syncthreads();

        // extract selected entries in this pos window (sel-index via cidx)
        const int g16 = pblk * 256 + pw * 8;
        const int s = (int)__ldg(&g_cidx[b * 1025 + g16]);
        const int e = (int)__ldg(&g_cidx[b * 1025 + g16 + 8]);
        for (int idx = s + w; idx < e; idx += 8) {
            uint32_t ent = __ldg(&g_sel[b * K + idx]);      // broadcast
            int p  = (int)(ent >> 16) - pbase;
            int rk = (int)(ent & 0xFFFFu);
            float val = tile[lane][p];                      // conflict-free column
            out[((size_t)b * K + rk) * (size_t)C + c0 + lane] = val;  // 128B coalesced
        }
        __syncthreads();
    }

    // wrap fallback (count < K) — no-op in practice
    if (cb > 0 && cb < K && pblk == 0) {
        for (int j = cb + t; j < K; j += 256) {
            uint32_t p = g_pos[b * K + (j % cb)];
            for (int cc = 0; cc < 32; cc++)
                out[((size_t)b * K + j) * (size_t)C + c0 + cc] =
                    __ldg(&x[((size_t)(b * C + c0 + cc)) * (size_t)L + p]);
        }
    }
}

extern "C" void kernel_launch(void* const* d_in, const int* in_sizes, int n_in,
                              void* d_out, int out_size) {
    const float* x = (const float*)d_in[0];
    int mi = n_in - 1;
    for (int i = 1; i < n_in; i++)
        if (in_sizes[i] == B * L) { mi = i; break; }
    const float* mask = (const float*)d_in[mi];
    float* out = (float*)d_out;

    static bool attr_done = false;
    if (!attr_done) {
        cudaFuncSetAttribute(select_kernel,
                             cudaFuncAttributeMaxDynamicSharedMemorySize, SMEM_SEL);
        attr_done = true;
    }

    select_kernel<<<B, 1024, SMEM_SEL>>>(mask, out, out_size);
    dim3 gg(4, 8, B);
    gather_kernel<<<gg, 256>>>(x, out);
}